// round 14
// baseline (speedup 1.0000x reference)
#include <cuda_runtime.h>
#include <cuda_fp16.h>

#define PNUM   512
#define BATCH  256
#define LPREDS 2
#define NLB    (LPREDS * BATCH)
#define NBLK   (2 * NLB)      // 1024 blocks
#define NGRP   32

__device__ unsigned g_val[NLB];   // zero-init sentinel pair-handshake; self-resets
__device__ float    g_sum;        // zero-init; reset via acquire-exch each run
__device__ unsigned g_cnt[NGRP];  // zero-init; self-reset by group finishers
__device__ unsigned g_done;       // zero-init; self-reset by winner

// 16B-group XOR swizzle: 8-lane LDS.128 phases (lane stride 32B) hit 8 distinct
// bank-quads instead of 2-way conflicting. Bijective within each 128B line-set.
__device__ __forceinline__ unsigned sgswz(unsigned g) { return g ^ ((g >> 3) & 7u); }

// smoothL1 on both components at once: d=p-q; u=min(|d|,1); acc += u*(|d|-0.5u)
// habs2 folds to operand modifier; HMNMX2 rides the alu pipe -> 3 fma-class ops.
__device__ __forceinline__ void sl1_h2(const unsigned pu, const unsigned qu,
                                       const __half2 one2, const __half2 nh2,
                                       __half2& acc) {
    __half2 p = *reinterpret_cast<const __half2*>(&pu);
    __half2 q = *reinterpret_cast<const __half2*>(&qu);
    __half2 d = __hsub2(p, q);           // fma
    __half2 a = __habs2(d);              // modifier
    __half2 u = __hmin2(a, one2);        // alu
    __half2 w = __hfma2(u, nh2, a);      // fma: |d| - 0.5u
    acc       = __hfma2(u, w, acc);      // fma: += u*(|d| - 0.5u)
}

__global__ __launch_bounds__(128, 7)
void poly_main(const float* __restrict__ pred, const float* __restrict__ gt,
               float* __restrict__ out) {
    __shared__ __align__(16) uint4   sg4[2 * PNUM / 4];   // gt doubled, 16B-swizzled
    __shared__ __align__(16) __half2 sp[4][PNUM];         // pred rotated by s=0..3
    __shared__ float wm[4];

    const int t   = threadIdx.x;
    const int bid = blockIdx.x;
    const int lb  = bid & (NLB - 1);
    const int h   = bid >> 9;              // which half of the 512 shifts
    const int b   = lb & (BATCH - 1);

    const float4* pv4 = (const float4*)(pred + (size_t)lb * PNUM * 2);  // 2 pts/elem
    const float4* gv4 = (const float4*)(gt   + (size_t)b  * PNUM * 2);

    unsigned* sgw = (unsigned*)sg4;

    #pragma unroll
    for (int k2 = t; k2 < 256; k2 += 128) {   // 2 iters; float4 = 2 points
        float4 g4 = gv4[k2];
        float4 p4 = pv4[k2];
        const int j = 2 * k2;                 // first point index (even)

        __half2 gh0 = __floats2half2_rn(g4.x, g4.y);
        __half2 gh1 = __floats2half2_rn(g4.z, g4.w);
        unsigned gb0 = *reinterpret_cast<unsigned*>(&gh0);
        unsigned gb1 = *reinterpret_cast<unsigned*>(&gh1);
        // point j -> swizzled group (j>>2), word (j&3); plus doubled copy at j+512
        unsigned ga = sgswz((unsigned)(j >> 2)) * 4u + (unsigned)(j & 3);
        unsigned gc = sgswz((unsigned)((j + PNUM) >> 2)) * 4u + (unsigned)(j & 3);
        sgw[ga]     = gb0;  sgw[ga + 1] = gb1;   // j, j+1 share a group (j even)
        sgw[gc]     = gb0;  sgw[gc + 1] = gb1;

        __half2 ph0 = __floats2half2_rn(p4.x, p4.y);
        __half2 ph1 = __floats2half2_rn(p4.z, p4.w);
        #pragma unroll
        for (int s = 0; s < 4; ++s) {         // sp[s][k] = p[(k+s) % 512]
            sp[s][(j      + PNUM - s) & (PNUM - 1)] = ph0;
            sp[s][(j + 1  + PNUM - s) & (PNUM - 1)] = ph1;
        }
    }
    __syncthreads();

    const int warp = t >> 5;
    const int lane = t & 31;
    const int r    = warp;                 // shift residue mod 4 handled by this warp
    const int s    = (4 - r) & 3;          // pred rotation so q base is 4-point aligned
    const int A    = h * 256 + r + 8 * lane;   // shift A; shift B = A + 4

    const unsigned gq0 = (unsigned)((A + s) >> 2);   // unswizzled Q base group
    const uint4* pf = reinterpret_cast<const uint4*>(sp[s]);

    const __half2 one2 = __floats2half2_rn(1.0f, 1.0f);
    const __half2 nh2  = __floats2half2_rn(-0.5f, -0.5f);
    const __half2 z2   = __floats2half2_rn(0.0f, 0.0f);

    __half2 hA0=z2,hA1=z2,hA2=z2,hA3=z2, hB0=z2,hB1=z2,hB2=z2,hB3=z2;
    float fAx=0.f, fAy=0.f, fBx=0.f, fBy=0.f;

    uint4 Pprev = pf[127];                 // cyclic wrap: B's m=0 terms use j=508..511

    for (int c = 0; c < 8; ++c) {          // 16 m-iters per fp16 chunk
        #pragma unroll
        for (int mm = 0; mm < 16; ++mm) {
            const int m = c * 16 + mm;
            uint4 P = pf[m];
            uint4 Q = sg4[sgswz(gq0 + (unsigned)m)];
            // shift A: pairs (p[4m+e], g[A+4m+e])
            sl1_h2(P.x, Q.x, one2, nh2, hA0);
            sl1_h2(P.y, Q.y, one2, nh2, hA1);
            sl1_h2(P.z, Q.z, one2, nh2, hA2);
            sl1_h2(P.w, Q.w, one2, nh2, hA3);
            // shift B = A+4: same Q, pred delayed one float4
            sl1_h2(Pprev.x, Q.x, one2, nh2, hB0);
            sl1_h2(Pprev.y, Q.y, one2, nh2, hB1);
            sl1_h2(Pprev.z, Q.z, one2, nh2, hB2);
            sl1_h2(Pprev.w, Q.w, one2, nh2, hB3);
            Pprev = P;
        }
        // drain fp16 chunk accumulators into fp32
        __half2 cA = __hadd2(__hadd2(hA0, hA1), __hadd2(hA2, hA3));
        __half2 cB = __hadd2(__hadd2(hB0, hB1), __hadd2(hB2, hB3));
        fAx += __low2float(cA);  fAy += __high2float(cA);
        fBx += __low2float(cB);  fBy += __high2float(cB);
        hA0=z2;hA1=z2;hA2=z2;hA3=z2; hB0=z2;hB1=z2;hB2=z2;hB3=z2;
    }

    float v = fminf(fAx + fAy, fBx + fBy);   // min over this thread's two shifts

    #pragma unroll
    for (int o = 16; o; o >>= 1)
        v = fminf(v, __shfl_xor_sync(0xffffffffu, v, o));
    if (lane == 0) wm[warp] = v;
    __syncthreads();

    if (t == 0) {
        float bv = fminf(fminf(wm[0], wm[1]), fminf(wm[2], wm[3]));
        // pair handshake per lb (relaxed exch; sentinel 0; bv > 0 so bits != 0)
        unsigned prev = atomicExch(&g_val[lb], __float_as_uint(bv));
        if (prev != 0u) {
            float combined = fminf(bv, __uint_as_float(prev));   // true lb-min
            g_val[lb] = 0u;   // self-reset (pair complete)
            // fire-and-forget RED: pipelines even same-address
            asm volatile("red.relaxed.gpu.global.add.f32 [%0], %1;"
                         :: "l"(&g_sum), "f"(combined) : "memory");
            // 32-way-split group counter: <=16 contenders per address
            unsigned gold;
            asm volatile("atom.acq_rel.gpu.global.add.u32 %0, [%1], %2;"
                         : "=r"(gold) : "l"(&g_cnt[lb & (NGRP - 1)]), "r"(1u) : "memory");
            if (gold == (NLB / NGRP) - 1) {          // 16th finisher of this group
                g_cnt[lb & (NGRP - 1)] = 0u;         // self-reset
                unsigned dn;
                asm volatile("atom.acq_rel.gpu.global.add.u32 %0, [%1], %2;"
                             : "=r"(dn) : "l"(&g_done), "r"(1u) : "memory");
                if (dn == NGRP - 1) {                // last group: all REDs visible
                    unsigned su;
                    asm volatile("atom.acquire.gpu.global.exch.b32 %0, [%1], %2;"
                                 : "=r"(su) : "l"(&g_sum), "r"(0u) : "memory");
                    *out = __uint_as_float(su) * (1.0f / ((float)PNUM * BATCH * LPREDS));
                    g_done = 0u;                     // self-reset
                }
            }
        }
    }
}

extern "C" void kernel_launch(void* const* d_in, const int* in_sizes, int n_in,
                              void* d_out, int out_size) {
    const float* pred = (const float*)d_in[0];   // (L, B, P, 2) fp32
    const float* gt   = (const float*)d_in[1];   // (B, P, 2) fp32
    float* out = (float*)d_out;

    poly_main<<<NBLK, 128>>>(pred, gt, out);
}

// round 15
// speedup vs baseline: 1.0523x; 1.0523x over previous
#include <cuda_runtime.h>
#include <cuda_fp16.h>

#define PNUM   512
#define BATCH  256
#define LPREDS 2
#define NLB    (LPREDS * BATCH)
#define NBLK   (2 * NLB)      // 1024 blocks
#define NGRP   32

__device__ unsigned g_val[NLB];   // zero-init sentinel pair-handshake; self-resets
__device__ float    g_sum;        // zero-init; reset via acquire-exch each run
__device__ unsigned g_cnt[NGRP];  // zero-init; self-reset by group finishers
__device__ unsigned g_done;       // zero-init; self-reset by winner

// smoothL1 on both components at once: d=p-q; u=min(|d|,1); acc += u*(|d|-0.5u)
// habs2 folds to operand modifier; HMNMX2 rides the alu pipe -> 3 fma-class ops.
__device__ __forceinline__ void sl1_h2(const unsigned pu, const unsigned qu,
                                       const __half2 one2, const __half2 nh2,
                                       __half2& acc) {
    __half2 p = *reinterpret_cast<const __half2*>(&pu);
    __half2 q = *reinterpret_cast<const __half2*>(&qu);
    __half2 d = __hsub2(p, q);           // fma
    __half2 a = __habs2(d);              // modifier
    __half2 u = __hmin2(a, one2);        // alu
    __half2 w = __hfma2(u, nh2, a);      // fma: |d| - 0.5u
    acc       = __hfma2(u, w, acc);      // fma: += u*(|d| - 0.5u)
}

__global__ __launch_bounds__(128, 7)
void poly_main(const float* __restrict__ pred, const float* __restrict__ gt,
               float* __restrict__ out) {
    __shared__ __align__(16) __half2 sg[2 * PNUM];        // gt doubled (cyclic)
    __shared__ __align__(16) __half2 sp[4][PNUM + 4];     // +4 pad: safe prefetch over-read
    __shared__ float wm[4];

    const int t   = threadIdx.x;
    const int bid = blockIdx.x;
    const int lb  = bid & (NLB - 1);
    const int h   = bid >> 9;              // which half of the 512 shifts
    const int b   = lb & (BATCH - 1);

    const float2* pv = (const float2*)(pred + (size_t)lb * PNUM * 2);
    const float2* gv = (const float2*)(gt   + (size_t)b  * PNUM * 2);

    #pragma unroll
    for (int k = t; k < PNUM; k += 128) {
        __half2 gh = __float22half2_rn(gv[k]);
        sg[k]        = gh;
        sg[k + PNUM] = gh;
        __half2 ph = __float22half2_rn(pv[k]);
        sp[0][k]               = ph;   // sp[s][j] = p[(j+s) % 512]
        sp[1][(k + 511) & 511] = ph;
        sp[2][(k + 510) & 511] = ph;
        sp[3][(k + 509) & 511] = ph;
    }
    __syncthreads();

    const int warp = t >> 5;
    const int lane = t & 31;
    const int r    = warp;                 // shift residue mod 4 handled by this warp
    const int s    = (4 - r) & 3;          // pred rotation so q base is 4-point aligned
    const int A    = h * 256 + r + 8 * lane;   // shift A; shift B = A + 4

    const uint4* qf = reinterpret_cast<const uint4*>(sg) + ((A + s) >> 2);
    const uint4* pf = reinterpret_cast<const uint4*>(sp[s]);

    const __half2 one2 = __floats2half2_rn(1.0f, 1.0f);
    const __half2 nh2  = __floats2half2_rn(-0.5f, -0.5f);
    const __half2 z2   = __floats2half2_rn(0.0f, 0.0f);

    __half2 hA0=z2,hA1=z2,hA2=z2,hA3=z2, hB0=z2,hB1=z2,hB2=z2,hB3=z2;
    float fAx=0.f, fAy=0.f, fBx=0.f, fBy=0.f;

    uint4 Pprev = pf[127];                 // cyclic wrap: B's m=0 terms use j=508..511
    uint4 P = pf[0];
    uint4 Q = qf[0];

    for (int c = 0; c < 8; ++c) {          // 16 m-iters per fp16 chunk
        #pragma unroll
        for (int mm = 0; mm < 16; ++mm) {
            const int m = c * 16 + mm;
            // prefetch next iteration's operands before using this one's
            // (m=127 -> pf[128]/qf[128] are in-bounds: sp padded, sg group<=255)
            uint4 Pn = pf[m + 1];
            uint4 Qn = qf[m + 1];
            // shift A: pairs (p[4m+e], g[A+4m+e])
            sl1_h2(P.x, Q.x, one2, nh2, hA0);
            sl1_h2(P.y, Q.y, one2, nh2, hA1);
            sl1_h2(P.z, Q.z, one2, nh2, hA2);
            sl1_h2(P.w, Q.w, one2, nh2, hA3);
            // shift B = A+4: same Q, pred delayed one float4
            sl1_h2(Pprev.x, Q.x, one2, nh2, hB0);
            sl1_h2(Pprev.y, Q.y, one2, nh2, hB1);
            sl1_h2(Pprev.z, Q.z, one2, nh2, hB2);
            sl1_h2(Pprev.w, Q.w, one2, nh2, hB3);
            Pprev = P;
            P = Pn;
            Q = Qn;
        }
        // drain fp16 chunk accumulators into fp32
        __half2 cA = __hadd2(__hadd2(hA0, hA1), __hadd2(hA2, hA3));
        __half2 cB = __hadd2(__hadd2(hB0, hB1), __hadd2(hB2, hB3));
        fAx += __low2float(cA);  fAy += __high2float(cA);
        fBx += __low2float(cB);  fBy += __high2float(cB);
        hA0=z2;hA1=z2;hA2=z2;hA3=z2; hB0=z2;hB1=z2;hB2=z2;hB3=z2;
    }

    float v = fminf(fAx + fAy, fBx + fBy);   // min over this thread's two shifts

    #pragma unroll
    for (int o = 16; o; o >>= 1)
        v = fminf(v, __shfl_xor_sync(0xffffffffu, v, o));
    if (lane == 0) wm[warp] = v;
    __syncthreads();

    if (t == 0) {
        float bv = fminf(fminf(wm[0], wm[1]), fminf(wm[2], wm[3]));
        // pair handshake per lb (relaxed exch; sentinel 0; bv > 0 so bits != 0)
        unsigned prev = atomicExch(&g_val[lb], __float_as_uint(bv));
        if (prev != 0u) {
            float combined = fminf(bv, __uint_as_float(prev));   // true lb-min
            g_val[lb] = 0u;   // self-reset (pair complete)
            // fire-and-forget RED: pipelines even same-address
            asm volatile("red.relaxed.gpu.global.add.f32 [%0], %1;"
                         :: "l"(&g_sum), "f"(combined) : "memory");
            // 32-way-split group counter: <=16 contenders per address
            unsigned gold;
            asm volatile("atom.acq_rel.gpu.global.add.u32 %0, [%1], %2;"
                         : "=r"(gold) : "l"(&g_cnt[lb & (NGRP - 1)]), "r"(1u) : "memory");
            if (gold == (NLB / NGRP) - 1) {          // 16th finisher of this group
                g_cnt[lb & (NGRP - 1)] = 0u;         // self-reset
                unsigned dn;
                asm volatile("atom.acq_rel.gpu.global.add.u32 %0, [%1], %2;"
                             : "=r"(dn) : "l"(&g_done), "r"(1u) : "memory");
                if (dn == NGRP - 1) {                // last group: all REDs visible
                    unsigned su;
                    asm volatile("atom.acquire.gpu.global.exch.b32 %0, [%1], %2;"
                                 : "=r"(su) : "l"(&g_sum), "r"(0u) : "memory");
                    *out = __uint_as_float(su) * (1.0f / ((float)PNUM * BATCH * LPREDS));
                    g_done = 0u;                     // self-reset
                }
            }
        }
    }
}

extern "C" void kernel_launch(void* const* d_in, const int* in_sizes, int n_in,
                              void* d_out, int out_size) {
    const float* pred = (const float*)d_in[0];   // (L, B, P, 2) fp32
    const float* gt   = (const float*)d_in[1];   // (B, P, 2) fp32
    float* out = (float*)d_out;

    poly_main<<<NBLK, 128>>>(pred, gt, out);
}